// round 14
// baseline (speedup 1.0000x reference)
#include <cuda_runtime.h>
#include <cstdint>
#include <math.h>

// Problem constants
#define H_HEADS 16
#define BATCH   2
#define L       1024
#define D       64
#define USAMP   7097
#define USEL    34
#define DMODEL  (H_HEADS * D)   // 1024
#define MROWS   (BATCH * L)     // 2048

// PV tiling
#define NCH 64
#define CHK 16

// ---------------- scratch (static device globals; no allocation) ----------------
__device__ float g_S[BATCH][L][L];
__device__ uint8_t g_cnt8[BATCH][L][16];
__device__ float g_M[BATCH][H_HEADS][L];
__device__ int   g_top[BATCH][H_HEADS][USEL];
__device__ int   g_sel[BATCH][H_HEADS][L];     // q -> selection slot (or -1)
__device__ float g_meanv[BATCH][D];
__device__ float g_pacc[BATCH][H_HEADS][USEL][NCH][64];  // per-chunk PV partials
__device__ float g_psum[BATCH][H_HEADS][USEL][NCH];      // per-chunk exp row sums
__device__ float g_delta[BATCH][H_HEADS][USEL][D];       // s1 - meanv
__device__ float g_E[BATCH][H_HEADS][USEL][DMODEL];      // delta @ W_h
__device__ float g_base[BATCH][DMODEL];                  // bias (init)
__device__ float g_basep[4][BATCH][DMODEL];              // K-split GEMV partials

// ---------------- threefry2x32 (JAX-compatible) ----------------
__device__ __forceinline__ uint32_t rotl32(uint32_t x, int d) {
    return (x << d) | (x >> (32 - d));
}

__device__ __forceinline__ void threefry2x32(uint32_t k0, uint32_t k1,
                                             uint32_t x0, uint32_t x1,
                                             uint32_t& o0, uint32_t& o1) {
    uint32_t ks2 = k0 ^ k1 ^ 0x1BD11BDAu;
    x0 += k0; x1 += k1;
#define TFR(r) { x0 += x1; x1 = rotl32(x1, (r)); x1 ^= x0; }
    TFR(13) TFR(15) TFR(26) TFR(6)   x0 += k1;  x1 += ks2 + 1u;
    TFR(17) TFR(29) TFR(16) TFR(24)  x0 += ks2; x1 += k0 + 2u;
    TFR(13) TFR(15) TFR(26) TFR(6)   x0 += k0;  x1 += k1 + 3u;
    TFR(17) TFR(29) TFR(16) TFR(24)  x0 += k1;  x1 += ks2 + 4u;
    TFR(13) TFR(15) TFR(26) TFR(6)   x0 += ks2; x1 += k0 + 5u;
#undef TFR
    o0 = x0; o1 = x1;
}

// ---------------- MUFU-free exp: range-reduced degree-7 poly (rel err ~5e-9) ----------------
__device__ __forceinline__ float fast_exp(float x) {
    float t = x * 1.4426950408889634f;
    float n = rintf(t);
    float g = (t - n) * 0.6931471805599453f;
    float p = 1.9841269841e-4f;
    p = fmaf(p, g, 1.3888888889e-3f);
    p = fmaf(p, g, 8.3333333333e-3f);
    p = fmaf(p, g, 4.1666666667e-2f);
    p = fmaf(p, g, 1.6666666667e-1f);
    p = fmaf(p, g, 0.5f);
    p = fmaf(p, g, 1.0f);
    p = fmaf(p, g, 1.0f);
    float s = __int_as_float((127 + (int)n) << 23);
    return p * s;
}

// ================= K1: mega prologue (hist FIRST | scores | meanv | sel-init | base-init) =================
// Histogram blocks are long serial threefry chains on only 32 blocks; placing them at
// bid 0-31 guarantees they start in wave 1 and overlap the 512 score blocks.
__global__ void __launch_bounds__(256) k_mega(const float* __restrict__ q,
                                              const float* __restrict__ k,
                                              const float* __restrict__ v,
                                              const float* __restrict__ bias) {
    __shared__ union {
        struct { float qt[64][68]; float kt[64][68]; } sc;   // transposed [d][row]
        uint32_t hist[L];
        float part[256];
    } sm;
    int bid = blockIdx.x;
    int tid = threadIdx.x;

    if (bid < 32) {
        // ---- sampled-index histogram for one (h, b) ----
        int h = bid & 15, b = bid >> 4;
        for (int j = tid; j < L; j += 256) sm.hist[j] = 0;
        __syncthreads();
        uint32_t hk0, hk1, s0, s1;
        threefry2x32(0u, 42u, 0u, (uint32_t)h, hk0, hk1);
        threefry2x32(hk0, hk1, 0u, 1u, s0, s1);
        for (int i = tid; i < USAMP; i += 256) {
            uint32_t b1, b2;
            threefry2x32(s0, s1, 0u, (uint32_t)(b * USAMP + i), b1, b2);
            atomicAdd(&sm.hist[(b1 ^ b2) & 1023u], 1u);
        }
        __syncthreads();
        for (int j = tid; j < L; j += 256)
            g_cnt8[b][j][h] = (uint8_t)sm.hist[j];
    } else if (bid < 544) {
        // ---- scores: S[b] = q[b] @ k[b]^T ----
        int t  = bid - 32;
        int b  = t >> 8;
        int i0 = ((t >> 4) & 15) * 64, j0 = (t & 15) * 64;
        for (int u = tid; u < 4096; u += 256) {
            int r = u >> 6, c = u & 63;
            sm.sc.qt[c][r] = q[((size_t)b * L + i0 + r) * D + c];
            sm.sc.kt[c][r] = k[((size_t)b * L + j0 + r) * D + c];
        }
        __syncthreads();
        int tx = tid & 15, ty = tid >> 4;
        float acc[4][4] = {};
#pragma unroll 8
        for (int d = 0; d < 64; d++) {
            float4 a4 = *(const float4*)&sm.sc.qt[d][ty * 4];
            float4 b4 = *(const float4*)&sm.sc.kt[d][tx * 4];
            float a[4] = {a4.x, a4.y, a4.z, a4.w};
            float bb[4] = {b4.x, b4.y, b4.z, b4.w};
#pragma unroll
            for (int r = 0; r < 4; r++)
#pragma unroll
                for (int c = 0; c < 4; c++)
                    acc[r][c] += a[r] * bb[c];
        }
#pragma unroll
        for (int r = 0; r < 4; r++)
#pragma unroll
            for (int c = 0; c < 4; c++)
                g_S[b][i0 + ty * 4 + r][j0 + tx * 4 + c] = acc[r][c];
    } else if (bid < 546) {
        int b = bid - 544;
        int d = tid & 63, g = tid >> 6;
        float s = 0.f;
        for (int kk = g; kk < L; kk += 4)
            s += v[((size_t)b * L + kk) * D + d];
        sm.part[tid] = s;
        __syncthreads();
        if (tid < 64)
            g_meanv[b][tid] = (sm.part[tid] + sm.part[tid + 64] + sm.part[tid + 128] + sm.part[tid + 192]) * (1.0f / 1024.0f);
    } else if (bid < 554) {
        int t = bid - 546;
        int base = (t * 256 + tid) * 16;
        int* sp = &g_sel[0][0][0];
#pragma unroll
        for (int e = 0; e < 16; e++) sp[base + e] = -1;
    } else {
        int b = bid - 554;
        int c4 = tid * 4;
        *(float4*)&g_base[b][c4] = *(const float4*)&bias[c4];
    }
}

// ================= K2: K-split base GEMV (blocks 0-31) + fused measure =================
__global__ void __launch_bounds__(256) k_measure_base(const float* __restrict__ W) {
    int bid = blockIdx.x;
    int tid = threadIdx.x;
    if (bid < 32) {
        int b  = bid >> 4;
        int kc = (bid >> 2) & 3;
        int c  = (bid & 3) * 256 + tid;
        __shared__ float mv[64];
        if (tid < 64) mv[tid] = g_meanv[b][tid];
        __syncthreads();
        int k0 = kc * 256;
        float a0 = 0.f, a1 = 0.f, a2 = 0.f, a3 = 0.f, a4 = 0.f, a5 = 0.f, a6 = 0.f, a7 = 0.f;
        for (int k = k0; k < k0 + 256; k += 8) {
            a0 += mv[(k)     & 63] * W[(size_t)(k)     * DMODEL + c];
            a1 += mv[(k + 1) & 63] * W[(size_t)(k + 1) * DMODEL + c];
            a2 += mv[(k + 2) & 63] * W[(size_t)(k + 2) * DMODEL + c];
            a3 += mv[(k + 3) & 63] * W[(size_t)(k + 3) * DMODEL + c];
            a4 += mv[(k + 4) & 63] * W[(size_t)(k + 4) * DMODEL + c];
            a5 += mv[(k + 5) & 63] * W[(size_t)(k + 5) * DMODEL + c];
            a6 += mv[(k + 6) & 63] * W[(size_t)(k + 6) * DMODEL + c];
            a7 += mv[(k + 7) & 63] * W[(size_t)(k + 7) * DMODEL + c];
        }
        g_basep[kc][b][c] = ((a0 + a1) + (a2 + a3)) + ((a4 + a5) + (a6 + a7));
    } else {
        int mb = bid - 32;
        int wid = tid >> 5, lane = tid & 31;
        int rowg = mb * 8 + wid;
        int b = rowg >> 10, row = rowg & 1023;
        const float* Srow = g_S[b][row];
        float mx[16], sv[16];
#pragma unroll
        for (int h = 0; h < 16; h++) { mx[h] = -3.4e38f; sv[h] = 0.f; }
        for (int j = lane; j < L; j += 32) {
            float s = Srow[j];
            uint4 c16 = *(const uint4*)&g_cnt8[b][j][0];
#define HP(wrd, base) { \
            int c0 = (wrd) & 255, c1 = ((wrd) >> 8) & 255, c2 = ((wrd) >> 16) & 255, c3 = (int)((wrd) >> 24); \
            if (c0) mx[(base)]     = fmaxf(mx[(base)],     s);  sv[(base)]     += (float)c0 * s; \
            if (c1) mx[(base) + 1] = fmaxf(mx[(base) + 1], s);  sv[(base) + 1] += (float)c1 * s; \
            if (c2) mx[(base) + 2] = fmaxf(mx[(base) + 2], s);  sv[(base) + 2] += (float)c2 * s; \
            if (c3) mx[(base) + 3] = fmaxf(mx[(base) + 3], s);  sv[(base) + 3] += (float)c3 * s; }
            HP(c16.x, 0) HP(c16.y, 4) HP(c16.z, 8) HP(c16.w, 12)
#undef HP
        }
#pragma unroll
        for (int h = 0; h < 16; h++) {
            float m = mx[h], s = sv[h];
#pragma unroll
            for (int off = 16; off; off >>= 1) {
                m = fmaxf(m, __shfl_down_sync(0xffffffffu, m, off));
                s += __shfl_down_sync(0xffffffffu, s, off);
            }
            if (lane == 0) g_M[b][h][row] = m - s / 7097.0f;
        }
    }
}

// ================= K3: top-34 via radix-select on packed 42-bit keys =================
__global__ void __launch_bounds__(1024) k_topk() {
    int h = blockIdx.x, b = blockIdx.y;
    int tid = threadIdx.x;
    __shared__ uint32_t hist[64];
    __shared__ uint32_t s_digit;
    __shared__ int s_rank;
    __shared__ int s_cnt;

    float val = g_M[b][h][tid];
    uint32_t ub = __float_as_uint(val);
    uint32_t u = (ub & 0x80000000u) ? ~ub : (ub | 0x80000000u);
    unsigned long long key = ((unsigned long long)u << 10) | (unsigned long long)(1023 - tid);

    unsigned long long prefix = 0ull;
    int rank = USEL;
    if (tid == 0) s_cnt = 0;

#pragma unroll
    for (int shift = 36; shift >= 0; shift -= 6) {
        if (tid < 64) hist[tid] = 0;
        __syncthreads();
        if ((key >> (shift + 6)) == prefix)
            atomicAdd(&hist[(uint32_t)(key >> shift) & 63u], 1u);
        __syncthreads();
        if (tid == 0) {
            int c = 0;
            for (int d = 63; d >= 0; d--) {
                c += (int)hist[d];
                if (c >= rank) {
                    s_digit = (uint32_t)d;
                    s_rank = rank - (c - (int)hist[d]);
                    break;
                }
            }
        }
        __syncthreads();
        prefix = (prefix << 6) | (unsigned long long)s_digit;
        rank = s_rank;
        __syncthreads();
    }

    if (key >= prefix) {
        int slot = atomicAdd(&s_cnt, 1);
        g_top[b][h][slot] = tid;
        g_sel[b][h][tid] = slot;
    }
}

// ================= K4: PV partials (CHK=16; low-reg inner loop; 6 blocks/SM) =================
__global__ void __launch_bounds__(256, 6) k_pv(const float* __restrict__ v) {
    __shared__ float vs[CHK][64];
    __shared__ float es[USEL][CHK];
    __shared__ int   tops[USEL];
    int ch = blockIdx.x, h = blockIdx.y, b = blockIdx.z;
    int k0 = ch * CHK;
    int tid = threadIdx.x;

    if (tid < USEL) tops[tid] = g_top[b][h][tid];
    {
        int u = tid;
        int kk = u >> 4, c4 = (u & 15) * 4;
        *(float4*)&vs[kk][c4] = *(const float4*)&v[((size_t)b * L + k0 + kk) * D + c4];
    }
    __syncthreads();

    for (int u = tid; u < USEL * CHK; u += 256) {
        int row = u >> 4, j = u & 15;
        es[row][j] = fast_exp(g_S[b][tops[row]][k0 + j] * 0.03125f);
    }
    __syncthreads();

    if (tid < USEL) {
        float s = 0.f;
#pragma unroll
        for (int j = 0; j < CHK; j++) s += es[tid][j];
        g_psum[b][h][tid][ch] = s;
    }

    int r = tid >> 6, d = tid & 63;
    float acc[9];
#pragma unroll
    for (int i = 0; i < 9; i++) acc[i] = 0.f;
    bool has9 = (r < 2);

    // load-then-consume per row: minimal live registers -> 6 blocks/SM
#pragma unroll
    for (int kk = 0; kk < CHK; kk += 4) {
        float v0 = vs[kk][d], v1 = vs[kk + 1][d], v2 = vs[kk + 2][d], v3 = vs[kk + 3][d];
#pragma unroll
        for (int i = 0; i < 8; i++) {
            float4 e = *(float4*)&es[r + i * 4][kk];
            acc[i] += e.x * v0 + e.y * v1 + e.z * v2 + e.w * v3;
        }
        if (has9) {
            float4 e = *(float4*)&es[r + 32][kk];
            acc[8] += e.x * v0 + e.y * v1 + e.z * v2 + e.w * v3;
        }
    }
#pragma unroll
    for (int i = 0; i < 8; i++)
        g_pacc[b][h][r + i * 4][ch][d] = acc[i];
    if (has9)
        g_pacc[b][h][r + 32][ch][d] = acc[8];
}

// ================= K5: delta = pacc_sum/psum_sum - meanv =================
__global__ void __launch_bounds__(64) k_delta() {
    int i = blockIdx.x, h = blockIdx.y, b = blockIdx.z;
    int tid = threadIdx.x;
    __shared__ float rsv;

    if (tid < 32) {
        float s = g_psum[b][h][i][tid] + g_psum[b][h][i][tid + 32];
#pragma unroll
        for (int off = 16; off; off >>= 1) s += __shfl_down_sync(0xffffffffu, s, off);
        if (tid == 0) rsv = 1.0f / s;
    }
    __syncthreads();

    float s = 0.f;
#pragma unroll
    for (int c = 0; c < NCH; c++) s += g_pacc[b][h][i][c][tid];
    g_delta[b][h][i][tid] = s * rsv - g_meanv[b][tid];
}

// ================= K6: correction GEMM  E[b][h] = delta[b][h] @ W[h*64:(h+1)*64, :] =================
__global__ void __launch_bounds__(128) k_corr(const float* __restrict__ W) {
    __shared__ float sd[USEL][64];
    int nc = blockIdx.x;
    int h  = blockIdx.y, b = blockIdx.z;
    int tid = threadIdx.x;
    int n0 = nc * 128;

    for (int u = tid; u < USEL * 64 / 2; u += 128) {
        int row = u >> 5, c2 = (u & 31) * 2;
        *(float2*)&sd[row][c2] = *(const float2*)&g_delta[b][h][row][c2];
    }
    __syncthreads();

    float acc[USEL];
#pragma unroll
    for (int i = 0; i < USEL; i++) acc[i] = 0.f;

    const float* Wp = W + (size_t)(h * 64) * DMODEL + n0 + tid;
#pragma unroll 4
    for (int k = 0; k < 64; k++) {
        float w = Wp[(size_t)k * DMODEL];
#pragma unroll
        for (int i = 0; i < USEL; i++)
            acc[i] += sd[i][k] * w;
    }
#pragma unroll
    for (int i = 0; i < USEL; i++)
        g_E[b][h][i][n0 + tid] = acc[i];
}

// ================= K7: assemble out = bias + GEMV partials + selected corrections =================
__global__ void __launch_bounds__(256) k_out(float* __restrict__ out) {
    __shared__ int sel[16];
    int bid = blockIdx.x;
    int b = bid >> 10, qq = bid & 1023;
    int tid = threadIdx.x;
    if (tid < 16) sel[tid] = g_sel[b][tid][qq];
    __syncthreads();

    int c4 = tid * 4;
    float4 val = *(const float4*)&g_base[b][c4];
#pragma unroll
    for (int kc = 0; kc < 4; kc++) {
        float4 p = *(const float4*)&g_basep[kc][b][c4];
        val.x += p.x; val.y += p.y; val.z += p.z; val.w += p.w;
    }
#pragma unroll
    for (int h = 0; h < 16; h++) {
        int i = sel[h];
        if (i >= 0) {
            float4 e = *(const float4*)&g_E[b][h][i][c4];
            val.x += e.x; val.y += e.y; val.z += e.z; val.w += e.w;
        }
    }
    *(float4*)&out[(size_t)(b * L + qq) * DMODEL + c4] = val;
}

// ---------------- launch ----------------
extern "C" void kernel_launch(void* const* d_in, const int* in_sizes, int n_in,
                              void* d_out, int out_size) {
    const float* q    = (const float*)d_in[0];
    const float* k    = (const float*)d_in[1];
    const float* v    = (const float*)d_in[2];
    const float* W    = (const float*)d_in[3];
    const float* bias = (const float*)d_in[4];
    float* out = (float*)d_out;

    k_mega<<<556, 256>>>(q, k, v, bias);

    k_measure_base<<<288, 256>>>(W);

    dim3 gT(H_HEADS, BATCH);
    k_topk<<<gT, 1024>>>();

    dim3 gPV(NCH, H_HEADS, BATCH);
    k_pv<<<gPV, 256>>>(v);

    dim3 gD(USEL, H_HEADS, BATCH);
    k_delta<<<gD, 64>>>();

    dim3 gC(8, H_HEADS, BATCH);
    k_corr<<<gC, 128>>>(W);

    k_out<<<MROWS, 256>>>(out);
}

// round 15
// speedup vs baseline: 1.1173x; 1.1173x over previous
#include <cuda_runtime.h>
#include <cstdint>
#include <math.h>

// Problem constants
#define H_HEADS 16
#define BATCH   2
#define L       1024
#define D       64
#define USAMP   7097
#define USEL    34
#define DMODEL  (H_HEADS * D)   // 1024
#define MROWS   (BATCH * L)     // 2048

// PV tiling
#define NCH 64
#define CHK 16

// ---------------- scratch (static device globals; no allocation) ----------------
__device__ float g_S[BATCH][L][L];
__device__ uint8_t g_cnt8[BATCH][L][16];
__device__ float g_M[BATCH][H_HEADS][L];
__device__ int   g_top[BATCH][H_HEADS][USEL];
__device__ int   g_sel[BATCH][H_HEADS][L];     // q -> selection slot (or -1)
__device__ float g_meanv[BATCH][D];
__device__ float g_pacc[BATCH][H_HEADS][USEL][NCH][64];  // per-chunk PV partials
__device__ float g_psum[BATCH][H_HEADS][USEL][NCH];      // per-chunk exp row sums
__device__ float g_delta[BATCH][H_HEADS][USEL][D];       // s1 - meanv
__device__ float g_E[BATCH][H_HEADS][USEL][DMODEL];      // delta @ W_h
__device__ float g_base[BATCH][DMODEL];                  // bias (init)
__device__ float g_basep[4][BATCH][DMODEL];              // K-split GEMV partials

// ---------------- threefry2x32 (JAX-compatible) ----------------
__device__ __forceinline__ uint32_t rotl32(uint32_t x, int d) {
    return (x << d) | (x >> (32 - d));
}

__device__ __forceinline__ void threefry2x32(uint32_t k0, uint32_t k1,
                                             uint32_t x0, uint32_t x1,
                                             uint32_t& o0, uint32_t& o1) {
    uint32_t ks2 = k0 ^ k1 ^ 0x1BD11BDAu;
    x0 += k0; x1 += k1;
#define TFR(r) { x0 += x1; x1 = rotl32(x1, (r)); x1 ^= x0; }
    TFR(13) TFR(15) TFR(26) TFR(6)   x0 += k1;  x1 += ks2 + 1u;
    TFR(17) TFR(29) TFR(16) TFR(24)  x0 += ks2; x1 += k0 + 2u;
    TFR(13) TFR(15) TFR(26) TFR(6)   x0 += k0;  x1 += k1 + 3u;
    TFR(17) TFR(29) TFR(16) TFR(24)  x0 += k1;  x1 += ks2 + 4u;
    TFR(13) TFR(15) TFR(26) TFR(6)   x0 += ks2; x1 += k0 + 5u;
#undef TFR
    o0 = x0; o1 = x1;
}

// ---------------- MUFU-free exp: range-reduced degree-7 poly (rel err ~5e-9) ----------------
__device__ __forceinline__ float fast_exp(float x) {
    float t = x * 1.4426950408889634f;
    float n = rintf(t);
    float g = (t - n) * 0.6931471805599453f;
    float p = 1.9841269841e-4f;
    p = fmaf(p, g, 1.3888888889e-3f);
    p = fmaf(p, g, 8.3333333333e-3f);
    p = fmaf(p, g, 4.1666666667e-2f);
    p = fmaf(p, g, 1.6666666667e-1f);
    p = fmaf(p, g, 0.5f);
    p = fmaf(p, g, 1.0f);
    p = fmaf(p, g, 1.0f);
    float s = __int_as_float((127 + (int)n) << 23);
    return p * s;
}

// ================= K1: mega prologue (scores | hist | meanv | sel-init | base-init) =================
__global__ void __launch_bounds__(256) k_mega(const float* __restrict__ q,
                                              const float* __restrict__ k,
                                              const float* __restrict__ v,
                                              const float* __restrict__ bias) {
    __shared__ union {
        struct { float qt[64][68]; float kt[64][68]; } sc;   // transposed [d][row]
        uint32_t hist[L];
        float part[256];
    } sm;
    int bid = blockIdx.x;
    int tid = threadIdx.x;

    if (bid < 512) {
        int b  = bid >> 8;
        int i0 = ((bid >> 4) & 15) * 64, j0 = (bid & 15) * 64;
        for (int u = tid; u < 4096; u += 256) {
            int r = u >> 6, c = u & 63;
            sm.sc.qt[c][r] = q[((size_t)b * L + i0 + r) * D + c];
            sm.sc.kt[c][r] = k[((size_t)b * L + j0 + r) * D + c];
        }
        __syncthreads();
        int tx = tid & 15, ty = tid >> 4;
        float acc[4][4] = {};
#pragma unroll 8
        for (int d = 0; d < 64; d++) {
            float4 a4 = *(const float4*)&sm.sc.qt[d][ty * 4];
            float4 b4 = *(const float4*)&sm.sc.kt[d][tx * 4];
            float a[4] = {a4.x, a4.y, a4.z, a4.w};
            float bb[4] = {b4.x, b4.y, b4.z, b4.w};
#pragma unroll
            for (int r = 0; r < 4; r++)
#pragma unroll
                for (int c = 0; c < 4; c++)
                    acc[r][c] += a[r] * bb[c];
        }
#pragma unroll
        for (int r = 0; r < 4; r++)
#pragma unroll
            for (int c = 0; c < 4; c++)
                g_S[b][i0 + ty * 4 + r][j0 + tx * 4 + c] = acc[r][c];
    } else if (bid < 544) {
        int t = bid - 512;
        int h = t & 15, b = t >> 4;
        for (int j = tid; j < L; j += 256) sm.hist[j] = 0;
        __syncthreads();
        uint32_t hk0, hk1, s0, s1;
        threefry2x32(0u, 42u, 0u, (uint32_t)h, hk0, hk1);
        threefry2x32(hk0, hk1, 0u, 1u, s0, s1);
        for (int i = tid; i < USAMP; i += 256) {
            uint32_t b1, b2;
            threefry2x32(s0, s1, 0u, (uint32_t)(b * USAMP + i), b1, b2);
            atomicAdd(&sm.hist[(b1 ^ b2) & 1023u], 1u);
        }
        __syncthreads();
        for (int j = tid; j < L; j += 256)
            g_cnt8[b][j][h] = (uint8_t)sm.hist[j];
    } else if (bid < 546) {
        int b = bid - 544;
        int d = tid & 63, g = tid >> 6;
        float s = 0.f;
        for (int kk = g; kk < L; kk += 4)
            s += v[((size_t)b * L + kk) * D + d];
        sm.part[tid] = s;
        __syncthreads();
        if (tid < 64)
            g_meanv[b][tid] = (sm.part[tid] + sm.part[tid + 64] + sm.part[tid + 128] + sm.part[tid + 192]) * (1.0f / 1024.0f);
    } else if (bid < 554) {
        int t = bid - 546;
        int base = (t * 256 + tid) * 16;
        int* sp = &g_sel[0][0][0];
#pragma unroll
        for (int e = 0; e < 16; e++) sp[base + e] = -1;
    } else {
        int b = bid - 554;
        int c4 = tid * 4;
        *(float4*)&g_base[b][c4] = *(const float4*)&bias[c4];
    }
}

// ================= K2: K-split base GEMV + fused measure (argmax-fallback masked max) =================
__global__ void __launch_bounds__(256) k_measure_base(const float* __restrict__ W) {
    int bid = blockIdx.x;
    int tid = threadIdx.x;
    if (bid < 32) {
        int b  = bid >> 4;
        int kc = (bid >> 2) & 3;
        int c  = (bid & 3) * 256 + tid;
        __shared__ float mv[64];
        if (tid < 64) mv[tid] = g_meanv[b][tid];
        __syncthreads();
        int k0 = kc * 256;
        float a0 = 0.f, a1 = 0.f, a2 = 0.f, a3 = 0.f, a4 = 0.f, a5 = 0.f, a6 = 0.f, a7 = 0.f;
        for (int k = k0; k < k0 + 256; k += 8) {
            a0 += mv[(k)     & 63] * W[(size_t)(k)     * DMODEL + c];
            a1 += mv[(k + 1) & 63] * W[(size_t)(k + 1) * DMODEL + c];
            a2 += mv[(k + 2) & 63] * W[(size_t)(k + 2) * DMODEL + c];
            a3 += mv[(k + 3) & 63] * W[(size_t)(k + 3) * DMODEL + c];
            a4 += mv[(k + 4) & 63] * W[(size_t)(k + 4) * DMODEL + c];
            a5 += mv[(k + 5) & 63] * W[(size_t)(k + 5) * DMODEL + c];
            a6 += mv[(k + 6) & 63] * W[(size_t)(k + 6) * DMODEL + c];
            a7 += mv[(k + 7) & 63] * W[(size_t)(k + 7) * DMODEL + c];
        }
        g_basep[kc][b][c] = ((a0 + a1) + (a2 + a3)) + ((a4 + a5) + (a6 + a7));
    } else {
        // ---- fused measure: one S pass, shared unmasked max + rare exact fallback ----
        int mb = bid - 32;
        int wid = tid >> 5, lane = tid & 31;
        int rowg = mb * 8 + wid;
        int b = rowg >> 10, row = rowg & 1023;
        const float* Srow = g_S[b][row];

        float mx = -3.4e38f;
        int jmx = 0;
        float sv[16];
#pragma unroll
        for (int h = 0; h < 16; h++) sv[h] = 0.f;

        for (int j = lane; j < L; j += 32) {
            float s = Srow[j];
            uint4 c16 = *(const uint4*)&g_cnt8[b][j][0];
            if (s > mx) { mx = s; jmx = j; }
#define SP(wrd, base) { \
            sv[(base)]     += (float)((wrd) & 255u)         * s; \
            sv[(base) + 1] += (float)(((wrd) >> 8) & 255u)  * s; \
            sv[(base) + 2] += (float)(((wrd) >> 16) & 255u) * s; \
            sv[(base) + 3] += (float)((wrd) >> 24)          * s; }
            SP(c16.x, 0) SP(c16.y, 4) SP(c16.z, 8) SP(c16.w, 12)
#undef SP
        }

        // butterfly argmax -> all lanes agree on (mx, jmx)
#pragma unroll
        for (int off = 16; off; off >>= 1) {
            float om = __shfl_xor_sync(0xffffffffu, mx, off);
            int   oj = __shfl_xor_sync(0xffffffffu, jmx, off);
            if (om > mx || (om == mx && oj < jmx)) { mx = om; jmx = oj; }
        }
        // reduce sums (lane 0 holds totals)
#pragma unroll
        for (int h = 0; h < 16; h++) {
            float s = sv[h];
#pragma unroll
            for (int off = 16; off; off >>= 1)
                s += __shfl_down_sync(0xffffffffu, s, off);
            sv[h] = s;
        }

        // which heads have an EMPTY bin at the argmax column? (rare: P ~ 1e-3)
        uint4 cj = *(const uint4*)&g_cnt8[b][jmx][0];
        uint32_t em = 0;
        {
            uint32_t w0 = cj.x, w1 = cj.y, w2 = cj.z, w3 = cj.w;
#pragma unroll
            for (int t = 0; t < 4; t++) {
                if (((w0 >> (t * 8)) & 255u) == 0) em |= 1u << t;
                if (((w1 >> (t * 8)) & 255u) == 0) em |= 1u << (4 + t);
                if (((w2 >> (t * 8)) & 255u) == 0) em |= 1u << (8 + t);
                if (((w3 >> (t * 8)) & 255u) == 0) em |= 1u << (12 + t);
            }
        }

#pragma unroll
        for (int h = 0; h < 16; h++) {
            float mh = mx;
            if (em & (1u << h)) {
                // exact masked rescan for this head only (warp-collective, rare)
                float m2 = -3.4e38f;
                for (int j = lane; j < L; j += 32) {
                    float s = Srow[j];
                    if (g_cnt8[b][j][h]) m2 = fmaxf(m2, s);
                }
#pragma unroll
                for (int off = 16; off; off >>= 1)
                    m2 = fmaxf(m2, __shfl_xor_sync(0xffffffffu, m2, off));
                mh = m2;
            }
            if (lane == 0) g_M[b][h][row] = mh - sv[h] / 7097.0f;
        }
    }
}

// ================= K3: top-34 via radix-select on packed 42-bit keys =================
__global__ void __launch_bounds__(1024) k_topk() {
    int h = blockIdx.x, b = blockIdx.y;
    int tid = threadIdx.x;
    __shared__ uint32_t hist[64];
    __shared__ uint32_t s_digit;
    __shared__ int s_rank;
    __shared__ int s_cnt;

    float val = g_M[b][h][tid];
    uint32_t ub = __float_as_uint(val);
    uint32_t u = (ub & 0x80000000u) ? ~ub : (ub | 0x80000000u);
    unsigned long long key = ((unsigned long long)u << 10) | (unsigned long long)(1023 - tid);

    unsigned long long prefix = 0ull;
    int rank = USEL;
    if (tid == 0) s_cnt = 0;

#pragma unroll
    for (int shift = 36; shift >= 0; shift -= 6) {
        if (tid < 64) hist[tid] = 0;
        __syncthreads();
        if ((key >> (shift + 6)) == prefix)
            atomicAdd(&hist[(uint32_t)(key >> shift) & 63u], 1u);
        __syncthreads();
        if (tid == 0) {
            int c = 0;
            for (int d = 63; d >= 0; d--) {
                c += (int)hist[d];
                if (c >= rank) {
                    s_digit = (uint32_t)d;
                    s_rank = rank - (c - (int)hist[d]);
                    break;
                }
            }
        }
        __syncthreads();
        prefix = (prefix << 6) | (unsigned long long)s_digit;
        rank = s_rank;
        __syncthreads();
    }

    if (key >= prefix) {
        int slot = atomicAdd(&s_cnt, 1);
        g_top[b][h][slot] = tid;
        g_sel[b][h][tid] = slot;
    }
}

// ================= K4: PV partials, 2 dims/thread (128 threads, R=9 x D=2) =================
__global__ void __launch_bounds__(128) k_pv(const float* __restrict__ v) {
    __shared__ float vs[CHK][64];     // 4 KB
    __shared__ float es[USEL][CHK];   // 2.2 KB
    __shared__ int   tops[USEL];
    int ch = blockIdx.x, h = blockIdx.y, b = blockIdx.z;
    int k0 = ch * CHK;
    int tid = threadIdx.x;

    if (tid < USEL) tops[tid] = g_top[b][h][tid];
    for (int u = tid; u < CHK * 64 / 4; u += 128) {
        int kk = u >> 4, c4 = (u & 15) * 4;
        *(float4*)&vs[kk][c4] = *(const float4*)&v[((size_t)b * L + k0 + kk) * D + c4];
    }
    __syncthreads();   // tops visible

    for (int u = tid; u < USEL * CHK; u += 128) {
        int row = u >> 4, j = u & 15;
        es[row][j] = fast_exp(g_S[b][tops[row]][k0 + j] * 0.03125f);
    }
    __syncthreads();

    if (tid < USEL) {
        float s = 0.f;
#pragma unroll
        for (int j = 0; j < CHK; j++) s += es[tid][j];
        g_psum[b][h][tid][ch] = s;
    }

    int r  = tid >> 5;            // 0..3 (warp-uniform)
    int d0 = (tid & 31) * 2;      // dim pair
    float acc[9][2];
#pragma unroll
    for (int i = 0; i < 9; i++) { acc[i][0] = 0.f; acc[i][1] = 0.f; }
    bool has9 = (r < 2);

#pragma unroll
    for (int kk = 0; kk < CHK; kk += 4) {
        float2 w0 = *(float2*)&vs[kk][d0];
        float2 w1 = *(float2*)&vs[kk + 1][d0];
        float2 w2 = *(float2*)&vs[kk + 2][d0];
        float2 w3 = *(float2*)&vs[kk + 3][d0];
#pragma unroll
        for (int i = 0; i < 8; i++) {
            float4 e = *(float4*)&es[r + i * 4][kk];
            acc[i][0] += e.x * w0.x + e.y * w1.x + e.z * w2.x + e.w * w3.x;
            acc[i][1] += e.x * w0.y + e.y * w1.y + e.z * w2.y + e.w * w3.y;
        }
        if (has9) {
            float4 e = *(float4*)&es[r + 32][kk];
            acc[8][0] += e.x * w0.x + e.y * w1.x + e.z * w2.x + e.w * w3.x;
            acc[8][1] += e.x * w0.y + e.y * w1.y + e.z * w2.y + e.w * w3.y;
        }
    }
#pragma unroll
    for (int i = 0; i < 8; i++) {
        float2 o; o.x = acc[i][0]; o.y = acc[i][1];
        *(float2*)&g_pacc[b][h][r + i * 4][ch][d0] = o;
    }
    if (has9) {
        float2 o; o.x = acc[8][0]; o.y = acc[8][1];
        *(float2*)&g_pacc[b][h][r + 32][ch][d0] = o;
    }
}

// ================= K5: delta = pacc_sum/psum_sum - meanv =================
__global__ void __launch_bounds__(64) k_delta() {
    int i = blockIdx.x, h = blockIdx.y, b = blockIdx.z;
    int tid = threadIdx.x;
    __shared__ float rsv;

    if (tid < 32) {
        float s = g_psum[b][h][i][tid] + g_psum[b][h][i][tid + 32];
#pragma unroll
        for (int off = 16; off; off >>= 1) s += __shfl_down_sync(0xffffffffu, s, off);
        if (tid == 0) rsv = 1.0f / s;
    }
    __syncthreads();

    float s = 0.f;
#pragma unroll
    for (int c = 0; c < NCH; c++) s += g_pacc[b][h][i][c][tid];
    g_delta[b][h][i][tid] = s * rsv - g_meanv[b][tid];
}

// ================= K6: correction GEMM  E[b][h] = delta[b][h] @ W[h*64:(h+1)*64, :] =================
__global__ void __launch_bounds__(128) k_corr(const float* __restrict__ W) {
    __shared__ float sd[USEL][64];
    int nc = blockIdx.x;
    int h  = blockIdx.y, b = blockIdx.z;
    int tid = threadIdx.x;
    int n0 = nc * 128;

    for (int u = tid; u < USEL * 64 / 2; u += 128) {
        int row = u >> 5, c2 = (u & 31) * 2;
        *(float2*)&sd[row][c2] = *(const float2*)&g_delta[b][h][row][c2];
    }
    __syncthreads();

    float acc[USEL];
#pragma unroll
    for (int i = 0; i < USEL; i++) acc[i] = 0.f;

    const float* Wp = W + (size_t)(h * 64) * DMODEL + n0 + tid;
#pragma unroll 4
    for (int k = 0; k < 64; k++) {
        float w = Wp[(size_t)k * DMODEL];
#pragma unroll
        for (int i = 0; i < USEL; i++)
            acc[i] += sd[i][k] * w;
    }
#pragma unroll
    for (int i = 0; i < USEL; i++)
        g_E[b][h][i][n0 + tid] = acc[i];
}

// ================= K7: assemble out = bias + GEMV partials + selected corrections =================
__global__ void __launch_bounds__(256) k_out(float* __restrict__ out) {
    __shared__ int sel[16];
    int bid = blockIdx.x;
    int b = bid >> 10, qq = bid & 1023;
    int tid = threadIdx.x;
    if (tid < 16) sel[tid] = g_sel[b][tid][qq];
    __syncthreads();

    int c4 = tid * 4;
    float4 val = *(const float4*)&g_base[b][c4];
#pragma unroll
    for (int kc = 0; kc < 4; kc++) {
        float4 p = *(const float4*)&g_basep[kc][b][c4];
        val.x += p.x; val.y += p.y; val.z += p.z; val.w += p.w;
    }
#pragma unroll
    for (int h = 0; h < 16; h++) {
        int i = sel[h];
        if (i >= 0) {
            float4 e = *(const float4*)&g_E[b][h][i][c4];
            val.x += e.x; val.y += e.y; val.z += e.z; val.w += e.w;
        }
    }
    *(float4*)&out[(size_t)(b * L + qq) * DMODEL + c4] = val;
}

// ---------------- launch ----------------
extern "C" void kernel_launch(void* const* d_in, const int* in_sizes, int n_in,
                              void* d_out, int out_size) {
    const float* q    = (const float*)d_in[0];
    const float* k    = (const float*)d_in[1];
    const float* v    = (const float*)d_in[2];
    const float* W    = (const float*)d_in[3];
    const float* bias = (const float*)d_in[4];
    float* out = (float*)d_out;

    k_mega<<<556, 256>>>(q, k, v, bias);

    k_measure_base<<<288, 256>>>(W);

    dim3 gT(H_HEADS, BATCH);
    k_topk<<<gT, 1024>>>();

    dim3 gPV(NCH, H_HEADS, BATCH);
    k_pv<<<gPV, 128>>>(v);

    dim3 gD(USEL, H_HEADS, BATCH);
    k_delta<<<gD, 64>>>();

    dim3 gC(8, H_HEADS, BATCH);
    k_corr<<<gC, 128>>>(W);

    k_out<<<MROWS, 256>>>(out);
}

// round 16
// speedup vs baseline: 1.1531x; 1.0320x over previous
#include <cuda_runtime.h>
#include <cstdint>
#include <math.h>

// Problem constants
#define H_HEADS 16
#define BATCH   2
#define L       1024
#define D       64
#define USAMP   7097
#define USEL    34
#define DMODEL  (H_HEADS * D)   // 1024
#define MROWS   (BATCH * L)     // 2048

// PV tiling: 32-key chunks, 1024 blocks total = single wave on 148 SMs
#define NCH 32
#define CHK 32

// ---------------- scratch (static device globals; no allocation) ----------------
__device__ float g_S[BATCH][L][L];
__device__ uint8_t g_cnt8[BATCH][L][16];
__device__ float g_M[BATCH][H_HEADS][L];
__device__ int   g_top[BATCH][H_HEADS][USEL];
__device__ int   g_sel[BATCH][H_HEADS][L];     // q -> selection slot (or -1)
__device__ float g_meanv[BATCH][D];
__device__ float g_pacc[BATCH][H_HEADS][USEL][NCH][64];  // per-chunk PV partials
__device__ float g_psum[BATCH][H_HEADS][USEL][NCH];      // per-chunk exp row sums
__device__ float g_delta[BATCH][H_HEADS][USEL][D];       // s1 - meanv
__device__ float g_E[BATCH][H_HEADS][USEL][DMODEL];      // delta @ W_h
__device__ float g_base[BATCH][DMODEL];                  // bias (init)
__device__ float g_basep[4][BATCH][DMODEL];              // K-split GEMV partials

// ---------------- threefry2x32 (JAX-compatible) ----------------
__device__ __forceinline__ uint32_t rotl32(uint32_t x, int d) {
    return (x << d) | (x >> (32 - d));
}

__device__ __forceinline__ void threefry2x32(uint32_t k0, uint32_t k1,
                                             uint32_t x0, uint32_t x1,
                                             uint32_t& o0, uint32_t& o1) {
    uint32_t ks2 = k0 ^ k1 ^ 0x1BD11BDAu;
    x0 += k0; x1 += k1;
#define TFR(r) { x0 += x1; x1 = rotl32(x1, (r)); x1 ^= x0; }
    TFR(13) TFR(15) TFR(26) TFR(6)   x0 += k1;  x1 += ks2 + 1u;
    TFR(17) TFR(29) TFR(16) TFR(24)  x0 += ks2; x1 += k0 + 2u;
    TFR(13) TFR(15) TFR(26) TFR(6)   x0 += k0;  x1 += k1 + 3u;
    TFR(17) TFR(29) TFR(16) TFR(24)  x0 += k1;  x1 += ks2 + 4u;
    TFR(13) TFR(15) TFR(26) TFR(6)   x0 += ks2; x1 += k0 + 5u;
#undef TFR
    o0 = x0; o1 = x1;
}

// ---------------- MUFU-free exp: range-reduced degree-7 poly (rel err ~5e-9) ----------------
__device__ __forceinline__ float fast_exp(float x) {
    float t = x * 1.4426950408889634f;
    float n = rintf(t);
    float g = (t - n) * 0.6931471805599453f;
    float p = 1.9841269841e-4f;
    p = fmaf(p, g, 1.3888888889e-3f);
    p = fmaf(p, g, 8.3333333333e-3f);
    p = fmaf(p, g, 4.1666666667e-2f);
    p = fmaf(p, g, 1.6666666667e-1f);
    p = fmaf(p, g, 0.5f);
    p = fmaf(p, g, 1.0f);
    p = fmaf(p, g, 1.0f);
    float s = __int_as_float((127 + (int)n) << 23);
    return p * s;
}

// ================= K1: mega prologue (scores | hist | meanv | sel-init | base-init) =================
__global__ void __launch_bounds__(256) k_mega(const float* __restrict__ q,
                                              const float* __restrict__ k,
                                              const float* __restrict__ v,
                                              const float* __restrict__ bias) {
    __shared__ union {
        struct { float qt[64][68]; float kt[64][68]; } sc;   // transposed [d][row]
        uint32_t hist[L];
        float part[256];
    } sm;
    int bid = blockIdx.x;
    int tid = threadIdx.x;

    if (bid < 512) {
        int b  = bid >> 8;
        int i0 = ((bid >> 4) & 15) * 64, j0 = (bid & 15) * 64;
        for (int u = tid; u < 4096; u += 256) {
            int r = u >> 6, c = u & 63;
            sm.sc.qt[c][r] = q[((size_t)b * L + i0 + r) * D + c];
            sm.sc.kt[c][r] = k[((size_t)b * L + j0 + r) * D + c];
        }
        __syncthreads();
        int tx = tid & 15, ty = tid >> 4;
        float acc[4][4] = {};
#pragma unroll 8
        for (int d = 0; d < 64; d++) {
            float4 a4 = *(const float4*)&sm.sc.qt[d][ty * 4];
            float4 b4 = *(const float4*)&sm.sc.kt[d][tx * 4];
            float a[4] = {a4.x, a4.y, a4.z, a4.w};
            float bb[4] = {b4.x, b4.y, b4.z, b4.w};
#pragma unroll
            for (int r = 0; r < 4; r++)
#pragma unroll
                for (int c = 0; c < 4; c++)
                    acc[r][c] += a[r] * bb[c];
        }
#pragma unroll
        for (int r = 0; r < 4; r++)
#pragma unroll
            for (int c = 0; c < 4; c++)
                g_S[b][i0 + ty * 4 + r][j0 + tx * 4 + c] = acc[r][c];
    } else if (bid < 544) {
        int t = bid - 512;
        int h = t & 15, b = t >> 4;
        for (int j = tid; j < L; j += 256) sm.hist[j] = 0;
        __syncthreads();
        uint32_t hk0, hk1, s0, s1;
        threefry2x32(0u, 42u, 0u, (uint32_t)h, hk0, hk1);
        threefry2x32(hk0, hk1, 0u, 1u, s0, s1);
        for (int i = tid; i < USAMP; i += 256) {
            uint32_t b1, b2;
            threefry2x32(s0, s1, 0u, (uint32_t)(b * USAMP + i), b1, b2);
            atomicAdd(&sm.hist[(b1 ^ b2) & 1023u], 1u);
        }
        __syncthreads();
        for (int j = tid; j < L; j += 256)
            g_cnt8[b][j][h] = (uint8_t)sm.hist[j];
    } else if (bid < 546) {
        int b = bid - 544;
        int d = tid & 63, g = tid >> 6;
        float s = 0.f;
        for (int kk = g; kk < L; kk += 4)
            s += v[((size_t)b * L + kk) * D + d];
        sm.part[tid] = s;
        __syncthreads();
        if (tid < 64)
            g_meanv[b][tid] = (sm.part[tid] + sm.part[tid + 64] + sm.part[tid + 128] + sm.part[tid + 192]) * (1.0f / 1024.0f);
    } else if (bid < 554) {
        int t = bid - 546;
        int base = (t * 256 + tid) * 16;
        int* sp = &g_sel[0][0][0];
#pragma unroll
        for (int e = 0; e < 16; e++) sp[base + e] = -1;
    } else {
        int b = bid - 554;
        int c4 = tid * 4;
        *(float4*)&g_base[b][c4] = *(const float4*)&bias[c4];
    }
}

// ================= K2: K-split base GEMV + fused measure (argmax-fallback masked max) =================
__global__ void __launch_bounds__(256) k_measure_base(const float* __restrict__ W) {
    int bid = blockIdx.x;
    int tid = threadIdx.x;
    if (bid < 32) {
        int b  = bid >> 4;
        int kc = (bid >> 2) & 3;
        int c  = (bid & 3) * 256 + tid;
        __shared__ float mv[64];
        if (tid < 64) mv[tid] = g_meanv[b][tid];
        __syncthreads();
        int k0 = kc * 256;
        float a0 = 0.f, a1 = 0.f, a2 = 0.f, a3 = 0.f, a4 = 0.f, a5 = 0.f, a6 = 0.f, a7 = 0.f;
        for (int k = k0; k < k0 + 256; k += 8) {
            a0 += mv[(k)     & 63] * W[(size_t)(k)     * DMODEL + c];
            a1 += mv[(k + 1) & 63] * W[(size_t)(k + 1) * DMODEL + c];
            a2 += mv[(k + 2) & 63] * W[(size_t)(k + 2) * DMODEL + c];
            a3 += mv[(k + 3) & 63] * W[(size_t)(k + 3) * DMODEL + c];
            a4 += mv[(k + 4) & 63] * W[(size_t)(k + 4) * DMODEL + c];
            a5 += mv[(k + 5) & 63] * W[(size_t)(k + 5) * DMODEL + c];
            a6 += mv[(k + 6) & 63] * W[(size_t)(k + 6) * DMODEL + c];
            a7 += mv[(k + 7) & 63] * W[(size_t)(k + 7) * DMODEL + c];
        }
        g_basep[kc][b][c] = ((a0 + a1) + (a2 + a3)) + ((a4 + a5) + (a6 + a7));
    } else {
        int mb = bid - 32;
        int wid = tid >> 5, lane = tid & 31;
        int rowg = mb * 8 + wid;
        int b = rowg >> 10, row = rowg & 1023;
        const float* Srow = g_S[b][row];

        float mx = -3.4e38f;
        int jmx = 0;
        float sv[16];
#pragma unroll
        for (int h = 0; h < 16; h++) sv[h] = 0.f;

        for (int j = lane; j < L; j += 32) {
            float s = Srow[j];
            uint4 c16 = *(const uint4*)&g_cnt8[b][j][0];
            if (s > mx) { mx = s; jmx = j; }
#define SP(wrd, base) { \
            sv[(base)]     += (float)((wrd) & 255u)         * s; \
            sv[(base) + 1] += (float)(((wrd) >> 8) & 255u)  * s; \
            sv[(base) + 2] += (float)(((wrd) >> 16) & 255u) * s; \
            sv[(base) + 3] += (float)((wrd) >> 24)          * s; }
            SP(c16.x, 0) SP(c16.y, 4) SP(c16.z, 8) SP(c16.w, 12)
#undef SP
        }

#pragma unroll
        for (int off = 16; off; off >>= 1) {
            float om = __shfl_xor_sync(0xffffffffu, mx, off);
            int   oj = __shfl_xor_sync(0xffffffffu, jmx, off);
            if (om > mx || (om == mx && oj < jmx)) { mx = om; jmx = oj; }
        }
#pragma unroll
        for (int h = 0; h < 16; h++) {
            float s = sv[h];
#pragma unroll
            for (int off = 16; off; off >>= 1)
                s += __shfl_down_sync(0xffffffffu, s, off);
            sv[h] = s;
        }

        uint4 cj = *(const uint4*)&g_cnt8[b][jmx][0];
        uint32_t em = 0;
        {
            uint32_t w0 = cj.x, w1 = cj.y, w2 = cj.z, w3 = cj.w;
#pragma unroll
            for (int t = 0; t < 4; t++) {
                if (((w0 >> (t * 8)) & 255u) == 0) em |= 1u << t;
                if (((w1 >> (t * 8)) & 255u) == 0) em |= 1u << (4 + t);
                if (((w2 >> (t * 8)) & 255u) == 0) em |= 1u << (8 + t);
                if (((w3 >> (t * 8)) & 255u) == 0) em |= 1u << (12 + t);
            }
        }

#pragma unroll
        for (int h = 0; h < 16; h++) {
            float mh = mx;
            if (em & (1u << h)) {
                float m2 = -3.4e38f;
                for (int j = lane; j < L; j += 32) {
                    float s = Srow[j];
                    if (g_cnt8[b][j][h]) m2 = fmaxf(m2, s);
                }
#pragma unroll
                for (int off = 16; off; off >>= 1)
                    m2 = fmaxf(m2, __shfl_xor_sync(0xffffffffu, m2, off));
                mh = m2;
            }
            if (lane == 0) g_M[b][h][row] = mh - sv[h] / 7097.0f;
        }
    }
}

// ================= K3: top-34 via radix-select on packed 42-bit keys =================
__global__ void __launch_bounds__(1024) k_topk() {
    int h = blockIdx.x, b = blockIdx.y;
    int tid = threadIdx.x;
    __shared__ uint32_t hist[64];
    __shared__ uint32_t s_digit;
    __shared__ int s_rank;
    __shared__ int s_cnt;

    float val = g_M[b][h][tid];
    uint32_t ub = __float_as_uint(val);
    uint32_t u = (ub & 0x80000000u) ? ~ub : (ub | 0x80000000u);
    unsigned long long key = ((unsigned long long)u << 10) | (unsigned long long)(1023 - tid);

    unsigned long long prefix = 0ull;
    int rank = USEL;
    if (tid == 0) s_cnt = 0;

#pragma unroll
    for (int shift = 36; shift >= 0; shift -= 6) {
        if (tid < 64) hist[tid] = 0;
        __syncthreads();
        if ((key >> (shift + 6)) == prefix)
            atomicAdd(&hist[(uint32_t)(key >> shift) & 63u], 1u);
        __syncthreads();
        if (tid == 0) {
            int c = 0;
            for (int d = 63; d >= 0; d--) {
                c += (int)hist[d];
                if (c >= rank) {
                    s_digit = (uint32_t)d;
                    s_rank = rank - (c - (int)hist[d]);
                    break;
                }
            }
        }
        __syncthreads();
        prefix = (prefix << 6) | (unsigned long long)s_digit;
        rank = s_rank;
        __syncthreads();
    }

    if (key >= prefix) {
        int slot = atomicAdd(&s_cnt, 1);
        g_top[b][h][slot] = tid;
        g_sel[b][h][tid] = slot;
    }
}

// ================= K4: PV partials — CHK=32, 1024 blocks (single wave), 4 dims/thread =================
__global__ void __launch_bounds__(128) k_pv(const float* __restrict__ v) {
    __shared__ float vs[CHK][64];     // 8 KB
    __shared__ float es[USEL][CHK];   // 4.25 KB
    __shared__ int   tops[USEL];
    int ch = blockIdx.x, h = blockIdx.y, b = blockIdx.z;
    int k0 = ch * CHK;
    int tid = threadIdx.x;

    if (tid < USEL) tops[tid] = g_top[b][h][tid];
    for (int u = tid; u < CHK * 64 / 4; u += 128) {   // 512 float4 slots, 4 iters
        int kk = u >> 4, c4 = (u & 15) * 4;
        *(float4*)&vs[kk][c4] = *(const float4*)&v[((size_t)b * L + k0 + kk) * D + c4];
    }
    __syncthreads();   // tops visible

    for (int u = tid; u < USEL * CHK; u += 128) {
        int row = u >> 5, j = u & 31;
        es[row][j] = fast_exp(g_S[b][tops[row]][k0 + j] * 0.03125f);
    }
    __syncthreads();

    if (tid < USEL) {
        float s = 0.f;
#pragma unroll
        for (int j = 0; j < CHK; j++) s += es[tid][j];
        g_psum[b][h][tid][ch] = s;
    }

    int r  = tid >> 4;            // 0..7 row group (rows stride 8)
    int d0 = (tid & 15) * 4;      // dim quad
    float acc[5][4];
#pragma unroll
    for (int i = 0; i < 5; i++)
#pragma unroll
        for (int dd = 0; dd < 4; dd++) acc[i][dd] = 0.f;
    bool has5 = (r < 2);          // rows r+32 valid only for r in {0,1}

#pragma unroll
    for (int kk = 0; kk < CHK; kk += 4) {
        float4 w0 = *(float4*)&vs[kk][d0];
        float4 w1 = *(float4*)&vs[kk + 1][d0];
        float4 w2 = *(float4*)&vs[kk + 2][d0];
        float4 w3 = *(float4*)&vs[kk + 3][d0];
#pragma unroll
        for (int jj = 0; jj < 4; jj++) {
            float4 e = *(float4*)&es[r + jj * 8][kk];
            acc[jj][0] += e.x * w0.x + e.y * w1.x + e.z * w2.x + e.w * w3.x;
            acc[jj][1] += e.x * w0.y + e.y * w1.y + e.z * w2.y + e.w * w3.y;
            acc[jj][2] += e.x * w0.z + e.y * w1.z + e.z * w2.z + e.w * w3.z;
            acc[jj][3] += e.x * w0.w + e.y * w1.w + e.z * w2.w + e.w * w3.w;
        }
        if (has5) {
            float4 e = *(float4*)&es[r + 32][kk];
            acc[4][0] += e.x * w0.x + e.y * w1.x + e.z * w2.x + e.w * w3.x;
            acc[4][1] += e.x * w0.y + e.y * w1.y + e.z * w2.y + e.w * w3.y;
            acc[4][2] += e.x * w0.z + e.y * w1.z + e.z * w2.z + e.w * w3.z;
            acc[4][3] += e.x * w0.w + e.y * w1.w + e.z * w2.w + e.w * w3.w;
        }
    }
#pragma unroll
    for (int jj = 0; jj < 4; jj++) {
        float4 o; o.x = acc[jj][0]; o.y = acc[jj][1]; o.z = acc[jj][2]; o.w = acc[jj][3];
        *(float4*)&g_pacc[b][h][r + jj * 8][ch][d0] = o;
    }
    if (has5) {
        float4 o; o.x = acc[4][0]; o.y = acc[4][1]; o.z = acc[4][2]; o.w = acc[4][3];
        *(float4*)&g_pacc[b][h][r + 32][ch][d0] = o;
    }
}

// ================= K5: delta = pacc_sum/psum_sum - meanv (NCH=32) =================
__global__ void __launch_bounds__(64) k_delta() {
    int i = blockIdx.x, h = blockIdx.y, b = blockIdx.z;
    int tid = threadIdx.x;
    __shared__ float rsv;

    if (tid < 32) {
        float s = g_psum[b][h][i][tid];
#pragma unroll
        for (int off = 16; off; off >>= 1) s += __shfl_down_sync(0xffffffffu, s, off);
        if (tid == 0) rsv = 1.0f / s;
    }
    __syncthreads();

    float s = 0.f;
#pragma unroll
    for (int c = 0; c < NCH; c++) s += g_pacc[b][h][i][c][tid];
    g_delta[b][h][i][tid] = s * rsv - g_meanv[b][tid];
}

// ================= K6: correction GEMM  E[b][h] = delta[b][h] @ W[h*64:(h+1)*64, :] =================
__global__ void __launch_bounds__(128) k_corr(const float* __restrict__ W) {
    __shared__ float sd[USEL][64];
    int nc = blockIdx.x;
    int h  = blockIdx.y, b = blockIdx.z;
    int tid = threadIdx.x;
    int n0 = nc * 128;

    for (int u = tid; u < USEL * 64 / 2; u += 128) {
        int row = u >> 5, c2 = (u & 31) * 2;
        *(float2*)&sd[row][c2] = *(const float2*)&g_delta[b][h][row][c2];
    }
    __syncthreads();

    float acc[USEL];
#pragma unroll
    for (int i = 0; i < USEL; i++) acc[i] = 0.f;

    const float* Wp = W + (size_t)(h * 64) * DMODEL + n0 + tid;
#pragma unroll 4
    for (int k = 0; k < 64; k++) {
        float w = Wp[(size_t)k * DMODEL];
#pragma unroll
        for (int i = 0; i < USEL; i++)
            acc[i] += sd[i][k] * w;
    }
#pragma unroll
    for (int i = 0; i < USEL; i++)
        g_E[b][h][i][n0 + tid] = acc[i];
}

// ================= K7: assemble out = bias + GEMV partials + selected corrections =================
__global__ void __launch_bounds__(256) k_out(float* __restrict__ out) {
    __shared__ int sel[16];
    int bid = blockIdx.x;
    int b = bid >> 10, qq = bid & 1023;
    int tid = threadIdx.x;
    if (tid < 16) sel[tid] = g_sel[b][tid][qq];
    __syncthreads();

    int c4 = tid * 4;
    float4 val = *(const float4*)&g_base[b][c4];
#pragma unroll
    for (int kc = 0; kc < 4; kc++) {
        float4 p = *(const float4*)&g_basep[kc][b][c4];
        val.x += p.x; val.y += p.y; val.z += p.z; val.w += p.w;
    }
#pragma unroll
    for (int h = 0; h < 16; h++) {
        int i = sel[h];
        if (i >= 0) {
            float4 e = *(const float4*)&g_E[b][h][i][c4];
            val.x += e.x; val.y += e.y; val.z += e.z; val.w += e.w;
        }
    }
    *(float4*)&out[(size_t)(b * L + qq) * DMODEL + c4] = val;
}

// ---------------- launch ----------------
extern "C" void kernel_launch(void* const* d_in, const int* in_sizes, int n_in,
                              void* d_out, int out_size) {
    const float* q    = (const float*)d_in[0];
    const float* k    = (const float*)d_in[1];
    const float* v    = (const float*)d_in[2];
    const float* W    = (const float*)d_in[3];
    const float* bias = (const float*)d_in[4];
    float* out = (float*)d_out;

    k_mega<<<556, 256>>>(q, k, v, bias);

    k_measure_base<<<288, 256>>>(W);

    dim3 gT(H_HEADS, BATCH);
    k_topk<<<gT, 1024>>>();

    dim3 gPV(NCH, H_HEADS, BATCH);
    k_pv<<<gPV, 128>>>(v);

    dim3 gD(USEL, H_HEADS, BATCH);
    k_delta<<<gD, 64>>>();

    dim3 gC(8, H_HEADS, BATCH);
    k_corr<<<gC, 128>>>(W);

    k_out<<<MROWS, 256>>>(out);
}